// round 4
// baseline (speedup 1.0000x reference)
#include <cuda_runtime.h>
#include <cuda_fp16.h>

// CapsuleLayer dynamic routing, B=512, R=640, C=10, O=16, I=8, 3 iters.
// Kernel 1: u_hat[b,r,c,o] = sum_i W[r,c,o,i] * x[b,r,i], stored fp16 to global scratch.
//           block-per-r (W in registers), two batches packed per fma.rn.f32x2.
// Kernel 2: block-per-batch routing; u_hat slice (100KB fp16) resident in SMEM,
//           all 3 routing iterations run out of SMEM.

#define BB 512
#define RR 640
#define CC 10
#define OO 16
#define COO 160
#define II 8

// 100 MiB fp16 scratch for u_hat (module-load allocation, permitted).
__device__ __half g_uhat[(size_t)BB * RR * COO];

// ---------- packed f32x2 helpers (sm_103a) ----------
__device__ __forceinline__ unsigned long long pack2(float lo, float hi) {
    unsigned long long r;
    asm("mov.b64 %0, {%1, %2};" : "=l"(r) : "f"(lo), "f"(hi));
    return r;
}
__device__ __forceinline__ void unpack2(unsigned long long v, float& lo, float& hi) {
    asm("mov.b64 {%0, %1}, %2;" : "=f"(lo), "=f"(hi) : "l"(v));
}
__device__ __forceinline__ unsigned long long fma2(unsigned long long a,
                                                   unsigned long long b,
                                                   unsigned long long c) {
    unsigned long long d;
    asm("fma.rn.f32x2 %0, %1, %2, %3;" : "=l"(d) : "l"(a), "l"(b), "l"(c));
    return d;
}

// =====================================================================
// Kernel 1: u_hat einsum. grid = 640 (one block per r), 320 threads.
// thread = grp*160 + co ; each thread owns one (c,o) with its 8 W values
// duplicated into f32x2 registers, and loops over batch PAIRS: x is staged
// in SMEM pre-packed as (x[2bp][i], x[2bp+1][i]) so each 8B smem read is
// one FFMA2 operand. 8 FFMA2 per iteration computes u_hat for 2 batches.
// =====================================================================
__global__ __launch_bounds__(320) void uhat_kernel(const float* __restrict__ x,
                                                   const float* __restrict__ W) {
    const int r = blockIdx.x;
    __shared__ float ws[COO * II];          // W[r] : [co*8 + i]
    __shared__ float xs[BB * II];           // packed: xs[bp*16 + i*2 + parity]
    const int tid = threadIdx.x;

    for (int idx = tid; idx < COO * II; idx += 320)
        ws[idx] = W[(size_t)r * (COO * II) + idx];
    for (int idx = tid; idx < BB * II; idx += 320) {
        int b  = idx >> 3;
        int ii = idx & 7;
        xs[(b >> 1) * 16 + ii * 2 + (b & 1)] = x[(size_t)b * (RR * II) + r * II + ii];
    }
    __syncthreads();

    const int co  = tid % COO;
    const int grp = tid / COO;              // 0 or 1 (interleaved batch pairs)

    unsigned long long wd[8];
#pragma unroll
    for (int i = 0; i < 8; i++) {
        float w = ws[co * 8 + i];
        wd[i] = pack2(w, w);
    }

    const unsigned long long* xsu = (const unsigned long long*)xs;
    __half* outp = g_uhat;

    for (int bp = grp; bp < BB / 2; bp += 2) {
        const ulonglong2* xp = (const ulonglong2*)(xsu + bp * 8);
        ulonglong2 q0 = xp[0];
        ulonglong2 q1 = xp[1];
        ulonglong2 q2 = xp[2];
        ulonglong2 q3 = xp[3];
        unsigned long long acc0 = 0ull, acc1 = 0ull;   // (0.0f, 0.0f) bit pattern
        acc0 = fma2(q0.x, wd[0], acc0);
        acc1 = fma2(q0.y, wd[1], acc1);
        acc0 = fma2(q1.x, wd[2], acc0);
        acc1 = fma2(q1.y, wd[3], acc1);
        acc0 = fma2(q2.x, wd[4], acc0);
        acc1 = fma2(q2.y, wd[5], acc1);
        acc0 = fma2(q3.x, wd[6], acc0);
        acc1 = fma2(q3.y, wd[7], acc1);
        float lo0, hi0, lo1, hi1;
        unpack2(acc0, lo0, hi0);
        unpack2(acc1, lo1, hi1);
        float ve = lo0 + lo1;   // batch 2bp
        float vo = hi0 + hi1;   // batch 2bp+1
        const int b0 = bp * 2;
        size_t base = ((size_t)b0 * RR + r) * COO + co;
        outp[base]                       = __float2half_rn(ve);
        outp[base + (size_t)RR * COO]    = __float2half_rn(vo);
    }
}

// =====================================================================
// Kernel 2: routing. grid = 512 (one block per batch), 640 threads,
// 231,104 B dynamic SMEM (<= 227 KB cap), 1 CTA/SM.
//
// SMEM map:
//   [0,      204800) u_hat tile, fp16, [r*160 + co]
//   [204800, 217600) c_ij, fp16, [r*10 + c]
//   [217600, 230400) UNION { redf: float[16][160] s_j partials ;
//                            a_s : fp16 [r*10+c] agreement }   (time-multiplexed)
//   [230400, 231040) sv: float[160]  (s_j then v_j in place)
//   [231040, 231080) nsc: float[10]  (squash scale per capsule)
//
// Mappings: thread-per-r (t=r) for softmax & b_ij (b_ij in registers);
// (rg = t/40, cq = t%40 = c*4+oquad) for the r-reductions: each thread
// sums 40 r's for 4 consecutive o's (LDS.64 per r).
// =====================================================================
#define SM_CIJ   204800
#define SM_ARED  217600
#define SM_SV    230400
#define SM_NSC   231040
#define SM_TOTAL 231104

__global__ __launch_bounds__(640, 1) void route_kernel(const float* __restrict__ bias,
                                                       float* __restrict__ out) {
    extern __shared__ unsigned char sm[];
    __half* uh   = (__half*)(sm);
    __half* cij  = (__half*)(sm + SM_CIJ);
    float*  redf = (float*)(sm + SM_ARED);
    __half* a_s  = (__half*)(sm + SM_ARED);
    float*  sv   = (float*)(sm + SM_SV);
    float*  nsc  = (float*)(sm + SM_NSC);

    const int b = blockIdx.x;
    const int t = threadIdx.x;

    // ---- stage u_hat[b] (100 KB fp16) into SMEM, coalesced 16B chunks ----
    {
        const uint4* src = (const uint4*)(g_uhat + (size_t)b * (RR * COO));
        uint4* dst = (uint4*)uh;
#pragma unroll
        for (int i = 0; i < 20; i++)
            dst[i * 640 + t] = src[i * 640 + t];
    }

    float bij[CC];
#pragma unroll
    for (int c = 0; c < CC; c++) bij[c] = 0.f;

    const int rg   = t / 40;      // 16 r-groups of 40 rows
    const int cq   = t % 40;      // c*4 + oquad
    const int c_of = cq >> 2;

    __syncthreads();

    for (int it = 0; it < 3; ++it) {
        // ---- c_ij = softmax(b_ij) over capsules, thread-per-r ----
        {
            float mx = bij[0];
#pragma unroll
            for (int c = 1; c < CC; c++) mx = fmaxf(mx, bij[c]);
            float e[CC];
            float s = 0.f;
#pragma unroll
            for (int c = 0; c < CC; c++) { e[c] = __expf(bij[c] - mx); s += e[c]; }
            float inv = 1.0f / s;
            __half2* cr = (__half2*)(cij + t * CC);
#pragma unroll
            for (int p = 0; p < 5; p++)
                cr[p] = __floats2half2_rn(e[2 * p] * inv, e[2 * p + 1] * inv);
        }
        __syncthreads();

        // ---- s_j partials: thread sums 40 r's for its 4 o's ----
        {
            float a0 = 0.f, a1 = 0.f, a2 = 0.f, a3 = 0.f;
            const int rbase = rg * 40;
#pragma unroll 4
            for (int rr = 0; rr < 40; rr++) {
                const int r = rbase + rr;
                uint2 h4 = *(const uint2*)(uh + r * COO + cq * 4);
                float  cw  = __half2float(cij[r * CC + c_of]);
                float2 flo = __half22float2(*reinterpret_cast<__half2*>(&h4.x));
                float2 fhi = __half22float2(*reinterpret_cast<__half2*>(&h4.y));
                a0 = fmaf(flo.x, cw, a0);
                a1 = fmaf(flo.y, cw, a1);
                a2 = fmaf(fhi.x, cw, a2);
                a3 = fmaf(fhi.y, cw, a3);
            }
            *(float4*)(redf + rg * COO + cq * 4) = make_float4(a0, a1, a2, a3);
        }
        __syncthreads();

        // ---- final s_j reduce (+bias) ----
        if (t < COO) {
            float s = bias[t];
#pragma unroll
            for (int g = 0; g < 16; g++) s += redf[g * COO + t];
            sv[t] = s;
        }
        __syncthreads();

        // ---- squash scale per capsule ----
        if (t < CC) {
            float n2 = 0.f;
#pragma unroll
            for (int o = 0; o < OO; o++) {
                float v = sv[t * OO + o];
                n2 = fmaf(v, v, n2);
            }
            float nrm = sqrtf(n2);
            nsc[t] = nrm / (1.0f + n2 + 1e-8f);
        }
        __syncthreads();
        if (t < COO) sv[t] *= nsc[t >> 4];
        __syncthreads();

        if (it < 2) {
            // ---- a_ij = <u_hat, v>: same rg/cq mapping; 4-lane shfl o-reduce ----
            const float4 vq = *(const float4*)(sv + cq * 4);
            const int rbase = rg * 40;
#pragma unroll 4
            for (int rr = 0; rr < 40; rr++) {
                const int r = rbase + rr;
                uint2 h4 = *(const uint2*)(uh + r * COO + cq * 4);
                float2 flo = __half22float2(*reinterpret_cast<__half2*>(&h4.x));
                float2 fhi = __half22float2(*reinterpret_cast<__half2*>(&h4.y));
                float p = fmaf(flo.x, vq.x,
                          fmaf(flo.y, vq.y,
                          fmaf(fhi.x, vq.z, fhi.y * vq.w)));
                p += __shfl_xor_sync(0xffffffffu, p, 1);
                p += __shfl_xor_sync(0xffffffffu, p, 2);
                if ((cq & 3) == 0) a_s[r * CC + c_of] = __float2half_rn(p);
            }
            __syncthreads();
            // ---- b_ij += a_ij, thread-per-r (registers) ----
            const __half2* ar = (const __half2*)(a_s + t * CC);
#pragma unroll
            for (int p = 0; p < 5; p++) {
                float2 f = __half22float2(ar[p]);
                bij[2 * p]     += f.x;
                bij[2 * p + 1] += f.y;
            }
            __syncthreads();
        }
    }

    // ---- output v_j [B,C,O] fp32 ----
    if (t < COO) out[(size_t)b * COO + t] = sv[t];
}

// =====================================================================
extern "C" void kernel_launch(void* const* d_in, const int* in_sizes, int n_in,
                              void* d_out, int out_size) {
    const float* x = nullptr;
    const float* W = nullptr;
    const float* bias = nullptr;
    for (int i = 0; i < n_in; i++) {
        if (in_sizes[i] == BB * RR * II)            x    = (const float*)d_in[i];
        else if (in_sizes[i] == RR * CC * OO * II)  W    = (const float*)d_in[i];
        else if (in_sizes[i] == CC * OO)            bias = (const float*)d_in[i];
    }

    cudaFuncSetAttribute(route_kernel, cudaFuncAttributeMaxDynamicSharedMemorySize,
                         SM_TOTAL);

    uhat_kernel<<<RR, 320>>>(x, W);
    route_kernel<<<BB, 640, SM_TOTAL>>>(bias, (float*)d_out);
}

// round 6
// speedup vs baseline: 1.0546x; 1.0546x over previous
#include <cuda_runtime.h>
#include <cuda_fp16.h>

// CapsuleLayer dynamic routing, B=512, R=640, C=10, O=16, I=8, 3 iters.
// Kernel 1: u_hat einsum -> fp16 global scratch. Thread owns 4 co, batch-pair
//           packed in fma.rn.f32x2, vectorized STG.64 output.
// Kernel 2: block-per-batch routing, u_hat tile (100KB fp16) SMEM-resident,
//           uint4 sweeps, it0 fast path, fused reduce+squash via shfl.

#define BB 512
#define RR 640
#define CC 10
#define OO 16
#define COO 160
#define II 8

__device__ __half g_uhat[(size_t)BB * RR * COO];

// ---------- packed f32x2 helpers (sm_103a) ----------
typedef unsigned long long ull;
__device__ __forceinline__ ull pack2(float lo, float hi) {
    ull r; asm("mov.b64 %0, {%1, %2};" : "=l"(r) : "f"(lo), "f"(hi)); return r;
}
__device__ __forceinline__ void unpack2(ull v, float& lo, float& hi) {
    asm("mov.b64 {%0, %1}, %2;" : "=f"(lo), "=f"(hi) : "l"(v));
}
__device__ __forceinline__ ull fma2(ull a, ull b, ull c) {
    ull d; asm("fma.rn.f32x2 %0, %1, %2, %3;" : "=l"(d) : "l"(a), "l"(b), "l"(c)); return d;
}
__device__ __forceinline__ ull add2(ull a, ull b) {
    ull d; asm("add.rn.f32x2 %0, %1, %2;" : "=l"(d) : "l"(a), "l"(b)); return d;
}
__device__ __forceinline__ ull h2f2(unsigned int h) {
    __half2 hh = *reinterpret_cast<__half2*>(&h);
    float2 f = __half22float2(hh);
    ull u; memcpy(&u, &f, 8); return u;
}

// =====================================================================
// Kernel 1: grid = 640 (block per r), 320 threads, 2 CTAs/SM.
// thread: cg = t%40 -> co quad [cg*4, cg*4+4); pl = t/40 -> batch-pair lane.
// Per batch-pair: 32 FFMA2 (4 co x 8 i, two batches packed), 2 STG.64.
// =====================================================================
__global__ __launch_bounds__(320, 2) void uhat_kernel(const float* __restrict__ x,
                                                      const float* __restrict__ W) {
    const int r = blockIdx.x;
    __shared__ float ws[COO * II];          // W[r]
    __shared__ float xs[BB * II];           // packed: xs[bp*16 + i*2 + parity]
    const int tid = threadIdx.x;

    for (int idx = tid; idx < COO * II; idx += 320)
        ws[idx] = W[(size_t)r * (COO * II) + idx];
    for (int idx = tid; idx < BB * II; idx += 320) {
        int bb = idx >> 3;
        int ii = idx & 7;
        xs[(bb >> 1) * 16 + ii * 2 + (bb & 1)] = x[(size_t)bb * (RR * II) + r * II + ii];
    }
    __syncthreads();

    const int cg = tid % 40;                // co quad index
    const int pl = tid / 40;                // 0..7

    ull wd[32];
#pragma unroll
    for (int j = 0; j < 4; j++)
#pragma unroll
        for (int i = 0; i < 8; i++) {
            float w = ws[(cg * 4 + j) * 8 + i];
            wd[j * 8 + i] = pack2(w, w);
        }

    const ull* xsu = (const ull*)xs;
    __half* outp = g_uhat;

    for (int bp = pl; bp < BB / 2; bp += 8) {
        const ulonglong2* xp = (const ulonglong2*)(xsu + bp * 8);
        ulonglong2 q0 = xp[0], q1 = xp[1], q2 = xp[2], q3 = xp[3];
        ull xi[8] = {q0.x, q0.y, q1.x, q1.y, q2.x, q2.y, q3.x, q3.y};
        ull a0 = 0ull, a1 = 0ull, a2 = 0ull, a3 = 0ull;
#pragma unroll
        for (int i = 0; i < 8; i++) {
            a0 = fma2(xi[i], wd[i],      a0);
            a1 = fma2(xi[i], wd[8 + i],  a1);
            a2 = fma2(xi[i], wd[16 + i], a2);
            a3 = fma2(xi[i], wd[24 + i], a3);
        }
        float e0, o0, e1, o1, e2, o2, e3, o3;
        unpack2(a0, e0, o0); unpack2(a1, e1, o1);
        unpack2(a2, e2, o2); unpack2(a3, e3, o3);

        const int b0 = bp * 2;
        size_t base = ((size_t)b0 * RR + r) * COO + cg * 4;

        __half2 h01 = __floats2half2_rn(e0, e1);
        __half2 h23 = __floats2half2_rn(e2, e3);
        uint2 st0; st0.x = *(unsigned*)&h01; st0.y = *(unsigned*)&h23;
        *(uint2*)(outp + base) = st0;

        __half2 g01 = __floats2half2_rn(o0, o1);
        __half2 g23 = __floats2half2_rn(o2, o3);
        uint2 st1; st1.x = *(unsigned*)&g01; st1.y = *(unsigned*)&g23;
        *(uint2*)(outp + base + (size_t)RR * COO) = st1;
    }
}

// =====================================================================
// Kernel 2: routing. grid=512 (block per batch), 640 threads, 231,040B smem.
//
// SMEM map:
//   [0,      204800) uh    fp16 [r*160+co]
//   [204800, 230400) UNION { cij float[640*10] ; redf float[32][160] ;
//                            a_s float[640*10] }   (disjoint phases)
//   [230400, 231040) sv float[160]
//
// Mappings: thread-per-r (t=r) for softmax & b_ij update (b_ij in regs);
// (rg=t/20 in [0,32), cq=t%20 = c*2+oh) for r-sweeps: 20 r's each, uint4
// (8 halves) per r. a_ij o-reduce: 1 shfl_xor(1) (pairs are adjacent
// even/odd lanes since rg*20+2c is even).
// =====================================================================
#define SM_UNI   204800
#define SM_SV    230400
#define SM_TOTAL 231040

__global__ __launch_bounds__(640, 1) void route_kernel(const float* __restrict__ bias,
                                                       float* __restrict__ out) {
    extern __shared__ unsigned char sm[];
    __half* uh   = (__half*)(sm);
    float*  cij  = (float*)(sm + SM_UNI);
    float*  redf = (float*)(sm + SM_UNI);
    float*  a_s  = (float*)(sm + SM_UNI);
    float*  sv   = (float*)(sm + SM_SV);

    const int b = blockIdx.x;
    const int t = threadIdx.x;

    // ---- stage u_hat[b] (100 KB fp16) into SMEM ----
    {
        const uint4* src = (const uint4*)(g_uhat + (size_t)b * (RR * COO));
        uint4* dst = (uint4*)uh;
#pragma unroll
        for (int i = 0; i < 20; i++)
            dst[i * 640 + t] = src[i * 640 + t];
    }

    const float biasv = (t < COO) ? bias[t] : 0.f;

    float bij[CC];
#pragma unroll
    for (int c = 0; c < CC; c++) bij[c] = 0.f;

    const int rg   = t / 20;                // 32 r-groups of 20 rows
    const int cq   = t % 20;                // c*2 + ohalf
    const int c_of = cq >> 1;
    const int oh   = cq & 1;
    const __half* uptr0 = uh + (rg * 20) * COO + cq * 8;

    __syncthreads();

    // ================= iteration 0: c_ij = 0.1 (constant) =================
    {
        ull s0 = 0ull, s1 = 0ull, s2 = 0ull, s3 = 0ull;
        const __half* p = uptr0;
#pragma unroll 10
        for (int rr = 0; rr < 20; rr++) {
            uint4 h = *(const uint4*)p; p += COO;
            s0 = add2(s0, h2f2(h.x));
            s1 = add2(s1, h2f2(h.y));
            s2 = add2(s2, h2f2(h.z));
            s3 = add2(s3, h2f2(h.w));
        }
        float f0, f1, f2, f3, f4, f5, f6, f7;
        unpack2(s0, f0, f1); unpack2(s1, f2, f3);
        unpack2(s2, f4, f5); unpack2(s3, f6, f7);
        float* rp = redf + rg * COO + cq * 8;
        *(float4*)(rp)     = make_float4(f0, f1, f2, f3);
        *(float4*)(rp + 4) = make_float4(f4, f5, f6, f7);
    }
    __syncthreads();

    for (int it = 0; it < 3; ++it) {
        // ---- fused reduce (+bias) + squash -> sv (and out on last iter) ----
        if (t < COO) {
            float s = 0.f;
#pragma unroll
            for (int g = 0; g < 32; g++) s += redf[g * COO + t];
            s = (it == 0) ? fmaf(s, 0.1f, biasv) : (s + biasv);
            float n2 = s * s;
            n2 += __shfl_xor_sync(0xffffffffu, n2, 1);
            n2 += __shfl_xor_sync(0xffffffffu, n2, 2);
            n2 += __shfl_xor_sync(0xffffffffu, n2, 4);
            n2 += __shfl_xor_sync(0xffffffffu, n2, 8);
            float scale = sqrtf(n2) / (1.0f + n2 + 1e-8f);
            float v = s * scale;
            sv[t] = v;
            if (it == 2) out[(size_t)b * COO + t] = v;
        }
        if (it == 2) break;
        __syncthreads();

        // ---- a_ij = <u_hat, v> per (r,c); write a_s (overlays redf) ----
        {
            const float4 lv0 = *(const float4*)(sv + cq * 8);
            const float4 lv1 = *(const float4*)(sv + cq * 8 + 4);
            const ull v0 = pack2(lv0.x, lv0.y), v1 = pack2(lv0.z, lv0.w);
            const ull v2 = pack2(lv1.x, lv1.y), v3 = pack2(lv1.z, lv1.w);
            const __half* p = uptr0;
#pragma unroll 10
            for (int rr = 0; rr < 20; rr++) {
                uint4 h = *(const uint4*)p; p += COO;
                ull pp = fma2(h2f2(h.x), v0, 0ull);
                pp = fma2(h2f2(h.y), v1, pp);
                pp = fma2(h2f2(h.z), v2, pp);
                pp = fma2(h2f2(h.w), v3, pp);
                float plo, phi; unpack2(pp, plo, phi);
                float ps = plo + phi;
                ps += __shfl_xor_sync(0xffffffffu, ps, 1);
                if (oh == 0) a_s[(rg * 20 + rr) * CC + c_of] = ps;
            }
        }
        __syncthreads();

        // ---- b_ij += a_ij (thread-per-r, registers) ----
        {
            const float2* ar = (const float2*)(a_s + t * CC);
#pragma unroll
            for (int q = 0; q < 5; q++) {
                float2 f = ar[q];
                bij[2 * q]     += f.x;
                bij[2 * q + 1] += f.y;
            }
        }
        __syncthreads();

        // ---- softmax(b_ij) -> cij fp32 (overlays a_s) ----
        {
            float e[CC];
            float ssum = 0.f;
#pragma unroll
            for (int c = 0; c < CC; c++) { e[c] = __expf(bij[c]); ssum += e[c]; }
            float inv = __fdividef(1.0f, ssum);
            float* cr = cij + t * CC;
#pragma unroll
            for (int c = 0; c < CC; c++) cr[c] = e[c] * inv;
        }
        __syncthreads();

        // ---- s_j partials: sum_r c_ij * u_hat (reads cij, acc in regs) ----
        {
            ull s0 = 0ull, s1 = 0ull, s2 = 0ull, s3 = 0ull;
            const float* cp = cij + (rg * 20) * CC + c_of;
            const __half* p = uptr0;
#pragma unroll 10
            for (int rr = 0; rr < 20; rr++) {
                uint4 h = *(const uint4*)p; p += COO;
                float cw = *cp; cp += CC;
                ull cwp = pack2(cw, cw);
                s0 = fma2(h2f2(h.x), cwp, s0);
                s1 = fma2(h2f2(h.y), cwp, s1);
                s2 = fma2(h2f2(h.z), cwp, s2);
                s3 = fma2(h2f2(h.w), cwp, s3);
            }
            __syncthreads();   // all cij reads done before redf overlay write
            float f0, f1, f2, f3, f4, f5, f6, f7;
            unpack2(s0, f0, f1); unpack2(s1, f2, f3);
            unpack2(s2, f4, f5); unpack2(s3, f6, f7);
            float* rp = redf + rg * COO + cq * 8;
            *(float4*)(rp)     = make_float4(f0, f1, f2, f3);
            *(float4*)(rp + 4) = make_float4(f4, f5, f6, f7);
        }
        __syncthreads();
    }
}

// =====================================================================
extern "C" void kernel_launch(void* const* d_in, const int* in_sizes, int n_in,
                              void* d_out, int out_size) {
    const float* x = nullptr;
    const float* W = nullptr;
    const float* bias = nullptr;
    for (int i = 0; i < n_in; i++) {
        if (in_sizes[i] == BB * RR * II)            x    = (const float*)d_in[i];
        else if (in_sizes[i] == RR * CC * OO * II)  W    = (const float*)d_in[i];
        else if (in_sizes[i] == CC * OO)            bias = (const float*)d_in[i];
    }

    cudaFuncSetAttribute(route_kernel, cudaFuncAttributeMaxDynamicSharedMemorySize,
                         SM_TOTAL);

    uhat_kernel<<<RR, 320>>>(x, W);
    route_kernel<<<BB, 640, SM_TOTAL>>>(bias, (float*)d_out);
}

// round 7
// speedup vs baseline: 1.1527x; 1.0931x over previous
#include <cuda_runtime.h>
#include <cuda_fp16.h>
#include <cstdint>

// CapsuleLayer dynamic routing, B=512, R=640, C=10, O=16, I=8, 3 iters.
// Kernel 1: u_hat einsum -> fp16 scratch. co-pair packed fma.rn.f32x2
//           (W regs halved vs batch-pair: no spills), x dup-packed in smem.
// Kernel 2: routing, 2-CTA cluster per batch (320 r's each, 102.4KB smem),
//           2 CTAs/SM; per-iter s_j halves exchanged via DSMEM + cluster.sync.

#define BB 512
#define RR 640
#define RHALF 320
#define CC 10
#define OO 16
#define COO 160
#define II 8

__device__ __half g_uhat[(size_t)BB * RR * COO];

typedef unsigned long long ull;
__device__ __forceinline__ ull pack2(float lo, float hi) {
    ull r; asm("mov.b64 %0, {%1, %2};" : "=l"(r) : "f"(lo), "f"(hi)); return r;
}
__device__ __forceinline__ void unpack2(ull v, float& lo, float& hi) {
    asm("mov.b64 {%0, %1}, %2;" : "=f"(lo), "=f"(hi) : "l"(v));
}
__device__ __forceinline__ ull fma2(ull a, ull b, ull c) {
    ull d; asm("fma.rn.f32x2 %0, %1, %2, %3;" : "=l"(d) : "l"(a), "l"(b), "l"(c)); return d;
}
__device__ __forceinline__ ull add2(ull a, ull b) {
    ull d; asm("add.rn.f32x2 %0, %1, %2;" : "=l"(d) : "l"(a), "l"(b)); return d;
}
__device__ __forceinline__ ull h2f2(unsigned int h) {
    __half2 hh = *reinterpret_cast<__half2*>(&h);
    float2 f = __half22float2(hh);
    ull u; memcpy(&u, &f, 8); return u;
}
__device__ __forceinline__ uint32_t smem_u32(const void* p) {
    uint32_t a;
    asm("{ .reg .u64 t; cvta.to.shared.u64 t, %1; cvt.u32.u64 %0, t; }" : "=r"(a) : "l"(p));
    return a;
}
__device__ __forceinline__ void dsmem_st_f32(uint32_t laddr, uint32_t rank, float v) {
    uint32_t raddr;
    asm volatile("mapa.shared::cluster.u32 %0, %1, %2;" : "=r"(raddr) : "r"(laddr), "r"(rank));
    asm volatile("st.shared::cluster.f32 [%0], %1;" :: "r"(raddr), "f"(v) : "memory");
}
#define CLUSTER_SYNC() do { \
    asm volatile("barrier.cluster.arrive.aligned;" ::: "memory"); \
    asm volatile("barrier.cluster.wait.aligned;"   ::: "memory"); } while (0)

// =====================================================================
// Kernel 1: grid=640 (block per r), 320 threads, 2 CTAs/SM, no spills.
// thread: cg=t%40 -> co quad; pl=t/40 -> batch lane (step 8).
// Per batch: 4 LDS.128 (dup'd x), 16 FFMA2 (2 co-pair accs), 1 STG.64.
// =====================================================================
__global__ __launch_bounds__(320, 2) void uhat_kernel(const float* __restrict__ x,
                                                      const float* __restrict__ W) {
    const int r = blockIdx.x;
    __shared__ float ws[COO * II];          // 5120B
    __shared__ ull   xs2[BB * II];          // 32768B: xs2[b*8+i] = (x,x) dup
    const int tid = threadIdx.x;

    for (int idx = tid; idx < COO * II; idx += 320)
        ws[idx] = W[(size_t)r * (COO * II) + idx];
    for (int idx = tid; idx < BB * 2; idx += 320) {
        int bb = idx >> 1, hf = idx & 1;
        float4 v = *(const float4*)(x + (size_t)bb * (RR * II) + r * II + hf * 4);
        ull* dst = xs2 + bb * 8 + hf * 4;
        dst[0] = pack2(v.x, v.x); dst[1] = pack2(v.y, v.y);
        dst[2] = pack2(v.z, v.z); dst[3] = pack2(v.w, v.w);
    }
    __syncthreads();

    const int cg = tid % 40;                // co quad base = cg*4
    const int pl = tid / 40;                // 0..7

    ull wp0[8], wp1[8];                     // co-pair packed W: 32 regs
#pragma unroll
    for (int i = 0; i < 8; i++) {
        wp0[i] = pack2(ws[(cg * 4 + 0) * 8 + i], ws[(cg * 4 + 1) * 8 + i]);
        wp1[i] = pack2(ws[(cg * 4 + 2) * 8 + i], ws[(cg * 4 + 3) * 8 + i]);
    }

    __half* outp = g_uhat;
    for (int bb = pl; bb < BB; bb += 8) {
        const ulonglong2* xp = (const ulonglong2*)(xs2 + bb * 8);
        ulonglong2 q0 = xp[0], q1 = xp[1], q2 = xp[2], q3 = xp[3];
        ull xi[8] = {q0.x, q0.y, q1.x, q1.y, q2.x, q2.y, q3.x, q3.y};
        ull a0 = 0ull, a1 = 0ull;
#pragma unroll
        for (int i = 0; i < 8; i++) {
            a0 = fma2(xi[i], wp0[i], a0);
            a1 = fma2(xi[i], wp1[i], a1);
        }
        float f0, f1, f2, f3;
        unpack2(a0, f0, f1);
        unpack2(a1, f2, f3);
        __half2 h01 = __floats2half2_rn(f0, f1);
        __half2 h23 = __floats2half2_rn(f2, f3);
        uint2 st; st.x = *(unsigned*)&h01; st.y = *(unsigned*)&h23;
        *(uint2*)(outp + ((size_t)bb * RR + r) * COO + cg * 4) = st;
    }
}

// =====================================================================
// Kernel 2: routing, cluster(2) per batch. grid=1024, 320 thr, 114,560B smem.
// SMEM per CTA:
//   [0,      102400) uh fp16 [r_local*160+co]   (320 r's)
//   [102400, 112640) UNION { redf f32[16][160] ; a_s/cij half[320*10] }
//   [112640, 113280) sv f32[160]
//   [113280, 114560) rbuf f32[2][160]  (parity-buffered peer s partials)
// Mappings: thread-per-r (t = local r) for b_ij+softmax (merged phase);
// (rg=t/20 in [0,16), cq=t%20=c*2+oh) sweeps: 20 r's, uint4 per r.
// =====================================================================
#define SM_UNI   102400
#define SM_SV    112640
#define SM_RBUF  113280
#define SM_TOTAL 114688

__global__ __launch_bounds__(320, 2) __cluster_dims__(2, 1, 1)
void route_kernel(const float* __restrict__ bias, float* __restrict__ out) {
    extern __shared__ unsigned char sm[];
    __half* uh   = (__half*)(sm);
    float*  redf = (float*)(sm + SM_UNI);
    __half* a_s  = (__half*)(sm + SM_UNI);
    __half* cijh = (__half*)(sm + SM_UNI);
    float*  sv   = (float*)(sm + SM_SV);
    float*  rbuf = (float*)(sm + SM_RBUF);

    const int b  = blockIdx.x >> 1;
    const uint32_t rk = blockIdx.x & 1;       // ctarank in cluster
    const int t  = threadIdx.x;

    // ---- stage this CTA's half of u_hat[b] (100 KB fp16) ----
    {
        const uint4* src = (const uint4*)(g_uhat + ((size_t)b * RR + rk * RHALF) * COO);
        uint4* dst = (uint4*)uh;
#pragma unroll
        for (int i = 0; i < 20; i++)
            dst[i * 320 + t] = src[i * 320 + t];
    }

    const float biasv = (t < COO) ? bias[t] : 0.f;

    float bij[CC];
#pragma unroll
    for (int c = 0; c < CC; c++) bij[c] = 0.f;

    const int rg   = t / 20;                  // 16 groups of 20 local r's
    const int cq   = t % 20;                  // c*2 + ohalf
    const int c_of = cq >> 1;
    const int oh   = cq & 1;
    const __half* uptr0 = uh + (rg * 20) * COO + cq * 8;
    const uint32_t rbuf_base = smem_u32(rbuf);

    __syncthreads();

    // ---- iteration-0 fast path: c_ij = 0.1 folded into reduce ----
    {
        ull s0 = 0ull, s1 = 0ull, s2 = 0ull, s3 = 0ull;
        const __half* p = uptr0;
#pragma unroll 10
        for (int rr = 0; rr < 20; rr++) {
            uint4 h = *(const uint4*)p; p += COO;
            s0 = add2(s0, h2f2(h.x)); s1 = add2(s1, h2f2(h.y));
            s2 = add2(s2, h2f2(h.z)); s3 = add2(s3, h2f2(h.w));
        }
        float f0, f1, f2, f3, f4, f5, f6, f7;
        unpack2(s0, f0, f1); unpack2(s1, f2, f3);
        unpack2(s2, f4, f5); unpack2(s3, f6, f7);
        float* rp = redf + rg * COO + cq * 8;
        *(float4*)(rp)     = make_float4(f0, f1, f2, f3);
        *(float4*)(rp + 4) = make_float4(f4, f5, f6, f7);
    }
    __syncthreads();

    for (int it = 0; it < 3; ++it) {
        const int par = it & 1;
        // ---- local reduce + DSMEM exchange ----
        float s_loc = 0.f;
        if (t < COO) {
#pragma unroll
            for (int g = 0; g < 16; g++) s_loc += redf[g * COO + t];
            dsmem_st_f32(rbuf_base + (par * COO + t) * 4, 1u - rk, s_loc);
        }
        CLUSTER_SYNC();
        // ---- total s + squash (identical on both CTAs) ----
        if (t < COO) {
            float s = s_loc + rbuf[par * COO + t];
            s = (it == 0) ? fmaf(s, 0.1f, biasv) : (s + biasv);
            float n2 = s * s;
            n2 += __shfl_xor_sync(0xffffffffu, n2, 1);
            n2 += __shfl_xor_sync(0xffffffffu, n2, 2);
            n2 += __shfl_xor_sync(0xffffffffu, n2, 4);
            n2 += __shfl_xor_sync(0xffffffffu, n2, 8);
            float scale = sqrtf(n2) / (1.0f + n2 + 1e-8f);
            float v = s * scale;
            sv[t] = v;
            if (it == 2 && rk == 0) out[(size_t)b * COO + t] = v;
        }
        if (it == 2) break;
        __syncthreads();

        // ---- a_ij = <u_hat, v>; writes a_s (over redf, consumed above) ----
        {
            const float4 lv0 = *(const float4*)(sv + cq * 8);
            const float4 lv1 = *(const float4*)(sv + cq * 8 + 4);
            const ull v0 = pack2(lv0.x, lv0.y), v1 = pack2(lv0.z, lv0.w);
            const ull v2 = pack2(lv1.x, lv1.y), v3 = pack2(lv1.z, lv1.w);
            const __half* p = uptr0;
#pragma unroll 10
            for (int rr = 0; rr < 20; rr++) {
                uint4 h = *(const uint4*)p; p += COO;
                ull pp = fma2(h2f2(h.x), v0, 0ull);
                pp = fma2(h2f2(h.y), v1, pp);
                pp = fma2(h2f2(h.z), v2, pp);
                pp = fma2(h2f2(h.w), v3, pp);
                float plo, phi; unpack2(pp, plo, phi);
                float ps = plo + phi;
                ps += __shfl_xor_sync(0xffffffffu, ps, 1);
                if (oh == 0) a_s[(rg * 20 + rr) * CC + c_of] = __float2half_rn(ps);
            }
        }
        __syncthreads();

        // ---- merged: b_ij += a_ij, softmax -> cijh (same thread, same idx) ----
        {
            const __half2* ar = (const __half2*)(a_s + t * CC);
            float2 f[5];
#pragma unroll
            for (int q = 0; q < 5; q++) f[q] = __half22float2(ar[q]);
#pragma unroll
            for (int q = 0; q < 5; q++) {
                bij[2 * q]     += f[q].x;
                bij[2 * q + 1] += f[q].y;
            }
            float e[CC]; float ssum = 0.f;
#pragma unroll
            for (int c = 0; c < CC; c++) { e[c] = __expf(bij[c]); ssum += e[c]; }
            float inv = __fdividef(1.0f, ssum);
            __half2* cw = (__half2*)(cijh + t * CC);
#pragma unroll
            for (int q = 0; q < 5; q++)
                cw[q] = __floats2half2_rn(e[2 * q] * inv, e[2 * q + 1] * inv);
        }
        __syncthreads();

        // ---- s_j partials: sum_r c_ij * u_hat -> redf (bar before overlay) ----
        {
            ull s0 = 0ull, s1 = 0ull, s2 = 0ull, s3 = 0ull;
            const __half* cp = cijh + (rg * 20) * CC + c_of;
            const __half* p = uptr0;
#pragma unroll 10
            for (int rr = 0; rr < 20; rr++) {
                uint4 h = *(const uint4*)p; p += COO;
                float cwv = __half2float(*cp); cp += CC;
                ull cwp = pack2(cwv, cwv);
                s0 = fma2(h2f2(h.x), cwp, s0);
                s1 = fma2(h2f2(h.y), cwp, s1);
                s2 = fma2(h2f2(h.z), cwp, s2);
                s3 = fma2(h2f2(h.w), cwp, s3);
            }
            __syncthreads();   // all cij reads done before redf overlay write
            float f0, f1, f2, f3, f4, f5, f6, f7;
            unpack2(s0, f0, f1); unpack2(s1, f2, f3);
            unpack2(s2, f4, f5); unpack2(s3, f6, f7);
            float* rp = redf + rg * COO + cq * 8;
            *(float4*)(rp)     = make_float4(f0, f1, f2, f3);
            *(float4*)(rp + 4) = make_float4(f4, f5, f6, f7);
        }
        __syncthreads();
    }
}

// =====================================================================
extern "C" void kernel_launch(void* const* d_in, const int* in_sizes, int n_in,
                              void* d_out, int out_size) {
    const float* x = nullptr;
    const float* W = nullptr;
    const float* bias = nullptr;
    for (int i = 0; i < n_in; i++) {
        if (in_sizes[i] == BB * RR * II)            x    = (const float*)d_in[i];
        else if (in_sizes[i] == RR * CC * OO * II)  W    = (const float*)d_in[i];
        else if (in_sizes[i] == CC * OO)            bias = (const float*)d_in[i];
    }

    cudaFuncSetAttribute(route_kernel, cudaFuncAttributeMaxDynamicSharedMemorySize,
                         SM_TOTAL);

    uhat_kernel<<<RR, 320>>>(x, W);
    route_kernel<<<BB * 2, 320, SM_TOTAL>>>(bias, (float*)d_out);
}